// round 1
// baseline (speedup 1.0000x reference)
#include <cuda_runtime.h>
#include <math.h>

#define BB 8
#define TT 1024
#define DD 512
#define HH 8
#define DH 64
#define MM 1024
#define BT (BB*TT)

// ---------------- scratch (device globals; allocation-free) ----------------
__device__ __align__(16) float g_x[BT*DD];                 // 16 MB  LN output
__device__ __align__(16) float g_q[BB*HH*TT*DH];           // 16 MB  [B,H,T,DH]
__device__ __align__(16) float g_k[BB*HH*TT*DH];
__device__ __align__(16) float g_v[BB*HH*TT*DH];
__device__ __align__(16) float g_p[BB*HH*TT*DH];
__device__ __align__(16) float g_sv[(size_t)BB*HH*TT*MM];  // 256 MB unshifted pos logits
__device__ __align__(16) float g_o[BB*HH*TT*DH];           // 16 MB  attn output

// ---------------- kernel 1: LayerNorm ----------------
__global__ void ln_kernel(const float* __restrict__ in,
                          const float* __restrict__ gamma,
                          const float* __restrict__ beta) {
    const int row = blockIdx.x;        // 0..BT-1
    const int tid = threadIdx.x;       // 256 threads, 2 elems each
    const float2 v = ((const float2*)(in + (size_t)row * DD))[tid];
    __shared__ float red[8];

    float s = v.x + v.y;
    #pragma unroll
    for (int o = 16; o; o >>= 1) s += __shfl_xor_sync(0xffffffffu, s, o);
    if ((tid & 31) == 0) red[tid >> 5] = s;
    __syncthreads();
    float mean = 0.f;
    #pragma unroll
    for (int i = 0; i < 8; i++) mean += red[i];
    mean *= (1.0f / DD);
    __syncthreads();

    const float dx = v.x - mean, dy = v.y - mean;
    float sq = dx*dx + dy*dy;
    #pragma unroll
    for (int o = 16; o; o >>= 1) sq += __shfl_xor_sync(0xffffffffu, sq, o);
    if ((tid & 31) == 0) red[tid >> 5] = sq;
    __syncthreads();
    float var = 0.f;
    #pragma unroll
    for (int i = 0; i < 8; i++) var += red[i];
    var *= (1.0f / DD);

    const float inv = rsqrtf(var + 1e-3f);
    const int c0 = tid * 2;
    float2 y;
    y.x = dx * inv * gamma[c0]   + beta[c0];
    y.y = dy * inv * gamma[c0+1] + beta[c0+1];
    ((float2*)g_x)[(size_t)row * (DD/2) + tid] = y;
}

// ---------------- kernel 2: per-head projection GEMM ----------------
// Out[b,h,t,o] = sum_i X[b,t,i] * W[h,i,o] (+ bias[h,o])
// grid: (BT/64, H), 256 threads, 64x64 tile, K=512 (BK=16), 4x4 per thread
__global__ void proj_kernel(const float* __restrict__ X,
                            const float* __restrict__ Wfull,
                            const float* __restrict__ bias,
                            float* __restrict__ Out) {
    const int rt = blockIdx.x;
    const int h  = blockIdx.y;
    const int bt0 = rt * 64;
    const float* W = Wfull + (size_t)h * DD * DH;

    __shared__ float As[64][16];
    __shared__ float Bs[16][64];

    const int tid = threadIdx.x;
    const int tx = tid & 15, ty = tid >> 4;
    const int ar = tid >> 2, ac = (tid & 3) * 4;
    const int br = tid >> 4, bc = (tid & 15) * 4;

    float acc[4][4] = {};
    for (int k0 = 0; k0 < DD; k0 += 16) {
        *(float4*)&As[ar][ac] = *(const float4*)&X[(size_t)(bt0 + ar) * DD + k0 + ac];
        *(float4*)&Bs[br][bc] = *(const float4*)&W[(size_t)(k0 + br) * DH + bc];
        __syncthreads();
        #pragma unroll
        for (int kk = 0; kk < 16; kk++) {
            float a[4], b[4];
            #pragma unroll
            for (int i = 0; i < 4; i++) a[i] = As[ty*4+i][kk];
            #pragma unroll
            for (int j = 0; j < 4; j++) b[j] = Bs[kk][tx*4+j];
            #pragma unroll
            for (int i = 0; i < 4; i++)
                #pragma unroll
                for (int j = 0; j < 4; j++)
                    acc[i][j] += a[i] * b[j];
        }
        __syncthreads();
    }

    const int b  = bt0 >> 10;
    const int t0 = bt0 & (TT-1);
    float bb[4];
    #pragma unroll
    for (int j = 0; j < 4; j++) bb[j] = bias ? bias[h*DH + tx*4 + j] : 0.f;
    #pragma unroll
    for (int i = 0; i < 4; i++) {
        const int t = t0 + ty*4 + i;
        const size_t base = ((size_t)(b*HH + h) * TT + t) * DH + tx*4;
        float4 o4;
        o4.x = acc[i][0] + bb[0];
        o4.y = acc[i][1] + bb[1];
        o4.z = acc[i][2] + bb[2];
        o4.w = acc[i][3] + bb[3];
        *(float4*)&Out[base] = o4;
    }
}

// ---------------- kernel 3: logits_v = (q + pos_bias_v) . p^T ----------------
// grid: (T/64, M/64, B*H), 256 threads, 64x64 output tile, K = DH = 64
__global__ void sv_kernel(const float* __restrict__ pos_bias_v) {
    const int n0 = blockIdx.x * 64;
    const int m0 = blockIdx.y * 64;
    const int bh = blockIdx.z;
    const int h  = bh & (HH-1);

    __shared__ float Qs[64][65];
    __shared__ float Ps[64][65];

    const int tid = threadIdx.x;
    const int tx = tid & 15, ty = tid >> 4;
    const int lr = tid >> 2, lc = (tid & 3) * 16;

    const size_t qbase = ((size_t)bh * TT + n0 + lr) * DH + lc;
    const size_t pbase = ((size_t)bh * TT + m0 + lr) * DH + lc;
    #pragma unroll
    for (int s = 0; s < 4; s++) {
        const float4 q4 = *(const float4*)&g_q[qbase + s*4];
        const float4 u4 = *(const float4*)&pos_bias_v[h*DH + lc + s*4];
        Qs[lr][lc+s*4+0] = q4.x + u4.x;
        Qs[lr][lc+s*4+1] = q4.y + u4.y;
        Qs[lr][lc+s*4+2] = q4.z + u4.z;
        Qs[lr][lc+s*4+3] = q4.w + u4.w;
        const float4 p4 = *(const float4*)&g_p[pbase + s*4];
        Ps[lr][lc+s*4+0] = p4.x;
        Ps[lr][lc+s*4+1] = p4.y;
        Ps[lr][lc+s*4+2] = p4.z;
        Ps[lr][lc+s*4+3] = p4.w;
    }
    __syncthreads();

    float acc[4][4] = {};
    #pragma unroll
    for (int kk = 0; kk < 64; kk++) {
        float a[4], b[4];
        #pragma unroll
        for (int i = 0; i < 4; i++) a[i] = Qs[ty*4+i][kk];
        #pragma unroll
        for (int j = 0; j < 4; j++) b[j] = Ps[tx*4+j][kk];
        #pragma unroll
        for (int i = 0; i < 4; i++)
            #pragma unroll
            for (int j = 0; j < 4; j++)
                acc[i][j] += a[i] * b[j];
    }

    #pragma unroll
    for (int i = 0; i < 4; i++) {
        const size_t base = ((size_t)bh * TT + n0 + ty*4 + i) * MM + m0 + tx*4;
        float4 o4; o4.x = acc[i][0]; o4.y = acc[i][1]; o4.z = acc[i][2]; o4.w = acc[i][3];
        *(float4*)&g_sv[base] = o4;
    }
}

// ---------------- kernel 4: fused shift + logits + softmax + P.V ----------------
// grid: (T/64, B*H), 256 threads. Flash-attention over m tiles of 64.
// Static smem exactly 48KB: Qs(q+u)[64][64], KT[c][m] 64x64 (reused for P), Vs[m][c].
__global__ void attn_kernel(const float* __restrict__ pos_bias_u) {
    __shared__ float Qs[64][64];
    __shared__ float KP[64][64];   // K transposed [c][m]; reused as P [n][m]
    __shared__ float Vs[64][64];   // [m][c]

    const int n0 = blockIdx.x * 64;
    const int bh = blockIdx.y;
    const int h  = bh & (HH-1);

    const int tid = threadIdx.x;
    const int tx = tid & 15, ty = tid >> 4;
    const int lr = tid >> 2, lc = (tid & 3) * 16;

    // load Q + pos_bias_u
    {
        const size_t qb = ((size_t)bh * TT + n0 + lr) * DH + lc;
        #pragma unroll
        for (int s = 0; s < 4; s++) {
            const float4 q4 = *(const float4*)&g_q[qb + s*4];
            const float4 u4 = *(const float4*)&pos_bias_u[h*DH + lc + s*4];
            float4 y; y.x = q4.x+u4.x; y.y = q4.y+u4.y; y.z = q4.z+u4.z; y.w = q4.w+u4.w;
            *(float4*)&Qs[lr][lc + s*4] = y;
        }
    }

    float Oa[4][4] = {};
    float mrow[4] = {-1e30f, -1e30f, -1e30f, -1e30f};
    float lrow[4] = {};
    const size_t svrow = (size_t)bh * TT;

    for (int mt = 0; mt < MM/64; mt++) {
        const int m0 = mt * 64;
        // load K (transposed into KP[c][m]) and V (row-major)
        {
            const size_t kb = ((size_t)bh * TT + m0 + lr) * DH + lc;
            #pragma unroll
            for (int s = 0; s < 4; s++) {
                const float4 k4 = *(const float4*)&g_k[kb + s*4];
                KP[lc+s*4+0][lr] = k4.x;
                KP[lc+s*4+1][lr] = k4.y;
                KP[lc+s*4+2][lr] = k4.z;
                KP[lc+s*4+3][lr] = k4.w;
                const float4 v4 = *(const float4*)&g_v[kb + s*4];
                *(float4*)&Vs[lr][lc + s*4] = v4;
            }
        }
        __syncthreads();

        // S = Qu . K^T
        float S[4][4] = {};
        #pragma unroll
        for (int kk = 0; kk < 64; kk++) {
            float a[4], b[4];
            #pragma unroll
            for (int i = 0; i < 4; i++) a[i] = Qs[ty*4+i][kk];
            #pragma unroll
            for (int j = 0; j < 4; j++) b[j] = KP[kk][tx*4+j];
            #pragma unroll
            for (int i = 0; i < 4; i++)
                #pragma unroll
                for (int j = 0; j < 4; j++)
                    S[i][j] += a[i] * b[j];
        }

        // add rel-shifted position logits and scale
        #pragma unroll
        for (int i = 0; i < 4; i++) {
            const int n = n0 + ty*4 + i;
            #pragma unroll
            for (int j = 0; j < 4; j++) {
                const int m = m0 + tx*4 + j;
                float sv;
                if (m <= n)            sv = g_sv[(svrow + n) * MM + (MM-1 - n + m)];
                else if (m == n + 1)   sv = 0.f;
                else                   sv = g_sv[(svrow + n + 1) * MM + (m - n - 2)];
                S[i][j] = (S[i][j] + sv) * 0.125f;   // 1/sqrt(64)
            }
        }

        // online softmax (row reductions within 16-lane half-warp group)
        #pragma unroll
        for (int i = 0; i < 4; i++) {
            float mx = fmaxf(fmaxf(S[i][0], S[i][1]), fmaxf(S[i][2], S[i][3]));
            #pragma unroll
            for (int o = 8; o; o >>= 1) mx = fmaxf(mx, __shfl_xor_sync(0xffffffffu, mx, o));
            const float mnew = fmaxf(mrow[i], mx);
            const float fac  = __expf(mrow[i] - mnew);
            mrow[i] = mnew;
            float ps = 0.f;
            #pragma unroll
            for (int j = 0; j < 4; j++) { S[i][j] = __expf(S[i][j] - mnew); ps += S[i][j]; }
            #pragma unroll
            for (int o = 8; o; o >>= 1) ps += __shfl_xor_sync(0xffffffffu, ps, o);
            lrow[i] = lrow[i] * fac + ps;
            #pragma unroll
            for (int j = 0; j < 4; j++) Oa[i][j] *= fac;
        }

        __syncthreads();   // everyone done reading K before KP becomes P
        #pragma unroll
        for (int i = 0; i < 4; i++)
            #pragma unroll
            for (int j = 0; j < 4; j++)
                KP[ty*4+i][tx*4+j] = S[i][j];
        __syncwarp();      // P rows of a ty-group are produced/consumed within one half-warp

        // O += P . V
        #pragma unroll
        for (int kk = 0; kk < 64; kk++) {
            float p[4], vv[4];
            #pragma unroll
            for (int i = 0; i < 4; i++) p[i] = KP[ty*4+i][kk];
            #pragma unroll
            for (int j = 0; j < 4; j++) vv[j] = Vs[kk][tx*4+j];
            #pragma unroll
            for (int i = 0; i < 4; i++)
                #pragma unroll
                for (int j = 0; j < 4; j++)
                    Oa[i][j] += p[i] * vv[j];
        }
        __syncthreads();   // before next tile overwrites KP/Vs
    }

    #pragma unroll
    for (int i = 0; i < 4; i++) {
        const float inv = 1.0f / lrow[i];
        const size_t ob = ((size_t)bh * TT + n0 + ty*4 + i) * DH + tx*4;
        float4 o4;
        o4.x = Oa[i][0]*inv; o4.y = Oa[i][1]*inv; o4.z = Oa[i][2]*inv; o4.w = Oa[i][3]*inv;
        *(float4*)&g_o[ob] = o4;
    }
}

// ---------------- kernel 5: output projection + bias + residual ----------------
// out[bt,d] = inputs[bt,d] + proj_b[d] + sum_k A[bt,k]*proj_k[k,d], k = h*64+o
__global__ void out_kernel(const float* __restrict__ inputs,
                           const float* __restrict__ projk,
                           const float* __restrict__ projb,
                           float* __restrict__ out) {
    const int bt0 = blockIdx.x * 64;
    const int d0  = blockIdx.y * 64;

    __shared__ float As[64][16];
    __shared__ float Bs[16][64];

    const int tid = threadIdx.x;
    const int tx = tid & 15, ty = tid >> 4;
    const int ar = tid >> 2, ac = (tid & 3) * 4;
    const int br = tid >> 4, bc = (tid & 15) * 4;
    const int b  = bt0 >> 10;
    const int t0 = bt0 & (TT-1);

    float acc[4][4] = {};
    for (int k0 = 0; k0 < DD; k0 += 16) {
        const int k = k0 + ac;
        const int h = k >> 6, o = k & 63;
        *(float4*)&As[ar][ac] =
            *(const float4*)&g_o[(((size_t)b*HH + h) * TT + (t0 + ar)) * DH + o];
        *(float4*)&Bs[br][bc] = *(const float4*)&projk[(size_t)(k0 + br) * DD + d0 + bc];
        __syncthreads();
        #pragma unroll
        for (int kk = 0; kk < 16; kk++) {
            float a[4], bvals[4];
            #pragma unroll
            for (int i = 0; i < 4; i++) a[i] = As[ty*4+i][kk];
            #pragma unroll
            for (int j = 0; j < 4; j++) bvals[j] = Bs[kk][tx*4+j];
            #pragma unroll
            for (int i = 0; i < 4; i++)
                #pragma unroll
                for (int j = 0; j < 4; j++)
                    acc[i][j] += a[i] * bvals[j];
        }
        __syncthreads();
    }

    #pragma unroll
    for (int i = 0; i < 4; i++) {
        const size_t base = (size_t)(bt0 + ty*4 + i) * DD + d0 + tx*4;
        const float4 r4 = *(const float4*)&inputs[base];
        float4 o4;
        o4.x = acc[i][0] + projb[d0+tx*4+0] + r4.x;
        o4.y = acc[i][1] + projb[d0+tx*4+1] + r4.y;
        o4.z = acc[i][2] + projb[d0+tx*4+2] + r4.z;
        o4.w = acc[i][3] + projb[d0+tx*4+3] + r4.w;
        *(float4*)&out[base] = o4;
    }
}

// ---------------- host ----------------
extern "C" void kernel_launch(void* const* d_in, const int* in_sizes, int n_in,
                              void* d_out, int out_size) {
    const float* inputs = (const float*)d_in[0];
    const float* pos    = (const float*)d_in[1];
    const float* gam    = (const float*)d_in[2];
    const float* bet    = (const float*)d_in[3];
    const float* w_q    = (const float*)d_in[4];
    const float* b_q    = (const float*)d_in[5];
    const float* w_k    = (const float*)d_in[6];
    const float* b_k    = (const float*)d_in[7];
    const float* w_v    = (const float*)d_in[8];
    const float* b_v    = (const float*)d_in[9];
    const float* w_p    = (const float*)d_in[10];
    const float* pbu    = (const float*)d_in[11];
    const float* pbv    = (const float*)d_in[12];
    const float* w_o    = (const float*)d_in[13];
    const float* b_o    = (const float*)d_in[14];
    float* out = (float*)d_out;

    float *px, *pq, *pk, *pv, *pp;
    cudaGetSymbolAddress((void**)&px, g_x);
    cudaGetSymbolAddress((void**)&pq, g_q);
    cudaGetSymbolAddress((void**)&pk, g_k);
    cudaGetSymbolAddress((void**)&pv, g_v);
    cudaGetSymbolAddress((void**)&pp, g_p);

    ln_kernel<<<BT, 256>>>(inputs, gam, bet);

    dim3 pg(BT/64, HH);
    proj_kernel<<<pg, 256>>>(px,  w_q, b_q,     pq);
    proj_kernel<<<pg, 256>>>(px,  w_k, b_k,     pk);
    proj_kernel<<<pg, 256>>>(px,  w_v, b_v,     pv);
    proj_kernel<<<pg, 256>>>(pos, w_p, nullptr, pp);

    sv_kernel<<<dim3(TT/64, MM/64, BB*HH), 256>>>(pbv);

    attn_kernel<<<dim3(TT/64, BB*HH), 256>>>(pbu);

    out_kernel<<<dim3(BT/64, DD/64), 256>>>(inputs, w_o, b_o, out);
}